// round 1
// baseline (speedup 1.0000x reference)
#include <cuda_runtime.h>
#include <math.h>

#define NB 32
#define NC 256
#define NH 64
#define NW 64
#define MIP 8
#define EPS 1e-5f

// Intermediates (no allocation allowed -> device globals)
__device__ float g_s [NB * NC * 128];   // strip-pooled+BN, concat [h|w] : 4 MB
__device__ float g_ah[NB * NC * NH];    // 2 MB
__device__ float g_aw[NB * NC * NW];    // 2 MB

// ---------------------------------------------------------------------------
// Kernel 1: per (b,c) slice -> row/col means -> depthwise conv3+conv7 -> BN
// One block per (b,c). 128 threads. 16KB smem tile.
// ---------------------------------------------------------------------------
__global__ __launch_bounds__(128) void k_reduce_strip(
    const float* __restrict__ x,
    const float* __restrict__ sph_w3, const float* __restrict__ sph_w7,
    const float* __restrict__ sph_g,  const float* __restrict__ sph_b,
    const float* __restrict__ sph_m,  const float* __restrict__ sph_v,
    const float* __restrict__ spw_w3, const float* __restrict__ spw_w7,
    const float* __restrict__ spw_g,  const float* __restrict__ spw_b,
    const float* __restrict__ spw_m,  const float* __restrict__ spw_v)
{
    __shared__ float tile[NH * NW];
    __shared__ float mrow[NH];   // x_h : mean over w
    __shared__ float mcol[NW];   // x_w : mean over h

    const int bc  = blockIdx.x;       // b*256 + c
    const int c   = bc & (NC - 1);
    const int tid = threadIdx.x;      // 0..127

    // Stage the 64x64 slice (1024 float4) into smem
    const float4* x4 = (const float4*)(x + (size_t)bc * (NH * NW));
    float4* t4 = (float4*)tile;
#pragma unroll
    for (int i = 0; i < 8; i++) t4[tid + i * 128] = x4[tid + i * 128];
    __syncthreads();

    if (tid < 64) {
        const int h = tid;
        float s = 0.f;
#pragma unroll
        for (int w = 0; w < 64; w++) s += tile[h * 64 + w];
        mrow[h] = s * (1.f / 64.f);
    } else {
        const int w = tid - 64;
        float s = 0.f;
#pragma unroll
        for (int h = 0; h < 64; h++) s += tile[h * 64 + w];
        mcol[w] = s * (1.f / 64.f);
    }
    __syncthreads();

    // Strip pool: (x + conv3(x) + conv7(x))/3, then BN. Threads 0..63 handle the
    // h-strip, 64..127 the w-strip.
    const int l = tid & 63;
    const float* src; const float* w3; const float* w7;
    float g, bb, mm, vv; int off;
    if (tid < 64) {
        src = mrow; w3 = sph_w3 + c * 3; w7 = sph_w7 + c * 7;
        g = sph_g[c]; bb = sph_b[c]; mm = sph_m[c]; vv = sph_v[c]; off = 0;
    } else {
        src = mcol; w3 = spw_w3 + c * 3; w7 = spw_w7 + c * 7;
        g = spw_g[c]; bb = spw_b[c]; mm = spw_m[c]; vv = spw_v[c]; off = 64;
    }

    float acc = src[l];   // identity term
#pragma unroll
    for (int j = 0; j < 3; j++) {
        int idx = l + j - 1;
        if (idx >= 0 && idx < 64) acc += src[idx] * w3[j];
    }
#pragma unroll
    for (int j = 0; j < 7; j++) {
        int idx = l + j - 3;
        if (idx >= 0 && idx < 64) acc += src[idx] * w7[j];
    }
    acc *= (1.f / 3.f);
    const float scale = g * rsqrtf(vv + EPS);
    g_s[(size_t)bc * 128 + off + l] = (acc - mm) * scale + bb;
}

// ---------------------------------------------------------------------------
// Kernel 2: per batch: conv1 (C->MIP) + BN1 + hswish + convh/convw (MIP->C)
//           + sigmoid -> g_ah, g_aw. One block per batch, 256 threads.
// ---------------------------------------------------------------------------
__global__ __launch_bounds__(256) void k_att(
    const float* __restrict__ conv1_w,
    const float* __restrict__ bn1_g, const float* __restrict__ bn1_b,
    const float* __restrict__ bn1_m, const float* __restrict__ bn1_v,
    const float* __restrict__ convh_w, const float* __restrict__ convw_w)
{
    __shared__ float w1s[MIP * NC];   // 8KB
    __shared__ float ys[MIP * 128];   // 4KB, post-hswish

    const int b   = blockIdx.x;
    const int tid = threadIdx.x;      // 0..255

#pragma unroll
    for (int i = 0; i < MIP; i++) w1s[tid + i * NC] = conv1_w[tid + i * NC];
    __syncthreads();

    // Phase A: y[m][l] = sum_c w1[m][c] * s[b][c][l]  (threads 0..127, l=tid)
    if (tid < 128) {
        const int l = tid;
        float acc[MIP];
#pragma unroll
        for (int m = 0; m < MIP; m++) acc[m] = 0.f;
        const float* sp = g_s + (size_t)b * NC * 128 + l;
        for (int cc = 0; cc < NC; cc++) {
            const float v = sp[(size_t)cc * 128];   // coalesced across l
#pragma unroll
            for (int m = 0; m < MIP; m++) acc[m] += w1s[m * NC + cc] * v;  // broadcast
        }
#pragma unroll
        for (int m = 0; m < MIP; m++) {
            const float scale = bn1_g[m] * rsqrtf(bn1_v[m] + EPS);
            const float val = (acc[m] - bn1_m[m]) * scale + bn1_b[m];
            // hswish
            ys[m * 128 + l] = val * fminf(fmaxf(val + 3.f, 0.f), 6.f) * (1.f / 6.f);
        }
    }
    __syncthreads();

    // Phase B: a_h[o][l] = sigmoid(sum_m convh_w[o][m] * y_h[m][l]); same for w.
    const int o = tid;
    float wh[MIP], ww[MIP];
#pragma unroll
    for (int m = 0; m < MIP; m++) {
        wh[m] = convh_w[o * MIP + m];
        ww[m] = convw_w[o * MIP + m];
    }
    const size_t base = ((size_t)b * NC + o) * 64;
#pragma unroll 4
    for (int l = 0; l < 64; l++) {
        float sh = 0.f, sw = 0.f;
#pragma unroll
        for (int m = 0; m < MIP; m++) {
            sh += wh[m] * ys[m * 128 + l];        // smem broadcast across threads
            sw += ww[m] * ys[m * 128 + 64 + l];
        }
        g_ah[base + l] = 1.f / (1.f + expf(-sh));
        g_aw[base + l] = 1.f / (1.f + expf(-sw));
    }
}

// ---------------------------------------------------------------------------
// Kernel 3: out = x * a_h[b,c,h] * a_w[b,c,w]   (float4 streaming)
// ---------------------------------------------------------------------------
__global__ __launch_bounds__(256) void k_apply(
    const float* __restrict__ x, float* __restrict__ out)
{
    const int i = blockIdx.x * blockDim.x + threadIdx.x;  // float4 index
    // total float4 = 32*256*64*64/4 = 8388608
    const int w4 = i & 15;          // which float4 along W
    const int h  = (i >> 4) & 63;
    const int bc = i >> 10;

    const float4 xv = ((const float4*)x)[i];
    const float  ah = g_ah[bc * 64 + h];
    const float4 aw = ((const float4*)g_aw)[bc * 16 + w4];

    float4 o;
    o.x = xv.x * ah * aw.x;
    o.y = xv.y * ah * aw.y;
    o.z = xv.z * ah * aw.z;
    o.w = xv.w * ah * aw.w;
    ((float4*)out)[i] = o;
}

// ---------------------------------------------------------------------------
extern "C" void kernel_launch(void* const* d_in, const int* in_sizes, int n_in,
                              void* d_out, int out_size)
{
    const float* x       = (const float*)d_in[0];
    const float* sph_w3  = (const float*)d_in[1];
    const float* sph_w7  = (const float*)d_in[2];
    const float* sph_g   = (const float*)d_in[3];
    const float* sph_b   = (const float*)d_in[4];
    const float* sph_m   = (const float*)d_in[5];
    const float* sph_v   = (const float*)d_in[6];
    const float* spw_w3  = (const float*)d_in[7];
    const float* spw_w7  = (const float*)d_in[8];
    const float* spw_g   = (const float*)d_in[9];
    const float* spw_b   = (const float*)d_in[10];
    const float* spw_m   = (const float*)d_in[11];
    const float* spw_v   = (const float*)d_in[12];
    const float* conv1_w = (const float*)d_in[13];
    const float* bn1_g   = (const float*)d_in[14];
    const float* bn1_b   = (const float*)d_in[15];
    const float* bn1_m   = (const float*)d_in[16];
    const float* bn1_v   = (const float*)d_in[17];
    const float* convh_w = (const float*)d_in[18];
    const float* convw_w = (const float*)d_in[19];
    float* out = (float*)d_out;

    k_reduce_strip<<<NB * NC, 128>>>(x,
        sph_w3, sph_w7, sph_g, sph_b, sph_m, sph_v,
        spw_w3, spw_w7, spw_g, spw_b, spw_m, spw_v);

    k_att<<<NB, 256>>>(conv1_w, bn1_g, bn1_b, bn1_m, bn1_v, convh_w, convw_w);

    const int total4 = NB * NC * NH * NW / 4;   // 8388608
    k_apply<<<total4 / 256, 256>>>(x, out);
}

// round 3
// speedup vs baseline: 1.5139x; 1.5139x over previous
#include <cuda_runtime.h>
#include <math.h>

#define NB 32
#define NC 256
#define NH 64
#define NW 64
#define MIP 8
#define EPS 1e-5f

// Intermediates (no allocation allowed -> device globals)
__device__ float g_s[NB * NC * 128];    // strip-pooled+BN, concat [h|w] : 4 MB
__device__ float g_y[NB * MIP * 128];   // post conv1+BN+hswish : 128 KB

// ---------------------------------------------------------------------------
// Kernel 1: per (b,c) slice -> row/col means -> depthwise conv3+conv7 -> BN
// One block per (b,c), 256 threads, register-resident reduction (no tile).
// ---------------------------------------------------------------------------
__global__ __launch_bounds__(256) void k_reduce_strip(
    const float* __restrict__ x,
    const float* __restrict__ sph_w3, const float* __restrict__ sph_w7,
    const float* __restrict__ sph_g,  const float* __restrict__ sph_b,
    const float* __restrict__ sph_m,  const float* __restrict__ sph_v,
    const float* __restrict__ spw_w3, const float* __restrict__ spw_w7,
    const float* __restrict__ spw_g,  const float* __restrict__ spw_b,
    const float* __restrict__ spw_m,  const float* __restrict__ spw_v)
{
    __shared__ __align__(16) float4 csum[256];   // per-thread column partials (4 KB)
    __shared__ float  mrow[NH];
    __shared__ float  mcol[NW];

    const int bc  = blockIdx.x;       // b*256 + c
    const int c   = bc & (NC - 1);
    const int tid = threadIdx.x;      // 0..255
    const int grp = tid >> 4;         // 0..15 (row-group)
    const int w4  = tid & 15;         // which float4 along W

    // 4 independent float4 loads: f = tid + i*256 -> h = grp + 16*i, col-chunk w4
    const float4* x4 = (const float4*)(x + (size_t)bc * (NH * NW));
    float4 v0 = x4[tid];
    float4 v1 = x4[tid + 256];
    float4 v2 = x4[tid + 512];
    float4 v3 = x4[tid + 768];

    // Column partials (same w4, 4 rows each)
    float4 cs;
    cs.x = v0.x + v1.x + v2.x + v3.x;
    cs.y = v0.y + v1.y + v2.y + v3.y;
    cs.z = v0.z + v1.z + v2.z + v3.z;
    cs.w = v0.w + v1.w + v2.w + v3.w;
    csum[tid] = cs;

    // Row chunk sums, reduce across the 16 lanes sharing grp (shfl, conflict-free)
    float r0 = v0.x + v0.y + v0.z + v0.w;
    float r1 = v1.x + v1.y + v1.z + v1.w;
    float r2 = v2.x + v2.y + v2.z + v2.w;
    float r3 = v3.x + v3.y + v3.z + v3.w;
#pragma unroll
    for (int m = 8; m >= 1; m >>= 1) {
        r0 += __shfl_xor_sync(0xffffffffu, r0, m);
        r1 += __shfl_xor_sync(0xffffffffu, r1, m);
        r2 += __shfl_xor_sync(0xffffffffu, r2, m);
        r3 += __shfl_xor_sync(0xffffffffu, r3, m);
    }
    if (w4 == 0) {
        mrow[grp]      = r0 * (1.f / 64.f);
        mrow[grp + 16] = r1 * (1.f / 64.f);
        mrow[grp + 32] = r2 * (1.f / 64.f);
        mrow[grp + 48] = r3 * (1.f / 64.f);
    }
    __syncthreads();

    // Column sums: thread t (<64) reduces column w=t over 16 groups.
    if (tid < 64) {
        const float* cf = (const float*)csum;
        float s = 0.f;
#pragma unroll
        for (int g = 0; g < 16; g++) s += cf[g * 64 + tid];
        mcol[tid] = s * (1.f / 64.f);
    }
    __syncthreads();

    // Strip pool: (x + conv3(x) + conv7(x))/3, then BN.
    if (tid < 128) {
        const int l = tid & 63;
        const float* src; const float* w3; const float* w7;
        float g, bb, mm, vv; int off;
        if (tid < 64) {
            src = mrow; w3 = sph_w3 + c * 3; w7 = sph_w7 + c * 7;
            g = sph_g[c]; bb = sph_b[c]; mm = sph_m[c]; vv = sph_v[c]; off = 0;
        } else {
            src = mcol; w3 = spw_w3 + c * 3; w7 = spw_w7 + c * 7;
            g = spw_g[c]; bb = spw_b[c]; mm = spw_m[c]; vv = spw_v[c]; off = 64;
        }

        float acc = src[l];
#pragma unroll
        for (int j = 0; j < 3; j++) {
            int idx = l + j - 1;
            if (idx >= 0 && idx < 64) acc += src[idx] * w3[j];
        }
#pragma unroll
        for (int j = 0; j < 7; j++) {
            int idx = l + j - 3;
            if (idx >= 0 && idx < 64) acc += src[idx] * w7[j];
        }
        acc *= (1.f / 3.f);
        const float scale = g * rsqrtf(vv + EPS);
        g_s[(size_t)bc * 128 + off + l] = (acc - mm) * scale + bb;
    }
}

// ---------------------------------------------------------------------------
// Kernel 2: per batch: conv1 (C->MIP) + BN1 + hswish -> g_y.
// One block per batch, 256 threads; channel dim split in two halves.
// ---------------------------------------------------------------------------
__global__ __launch_bounds__(256) void k_y(
    const float* __restrict__ conv1_w,
    const float* __restrict__ bn1_g, const float* __restrict__ bn1_b,
    const float* __restrict__ bn1_m, const float* __restrict__ bn1_v)
{
    __shared__ float w1s[MIP * NC];       // 8 KB
    __shared__ float part[2 * MIP * 128]; // 8 KB

    const int b    = blockIdx.x;
    const int tid  = threadIdx.x;
    const int half = tid >> 7;            // 0 or 1 (channel half)
    const int l    = tid & 127;

#pragma unroll
    for (int i = 0; i < MIP; i++) w1s[tid + i * NC] = conv1_w[tid + i * NC];
    __syncthreads();

    float acc[MIP];
#pragma unroll
    for (int m = 0; m < MIP; m++) acc[m] = 0.f;

    const float* sp = g_s + (size_t)b * NC * 128 + half * 128 * 128 + l;
#pragma unroll 4
    for (int cc = 0; cc < 128; cc++) {
        const float v = sp[(size_t)cc * 128];   // coalesced across l
#pragma unroll
        for (int m = 0; m < MIP; m++) acc[m] += w1s[m * NC + half * 128 + cc] * v;
    }
#pragma unroll
    for (int m = 0; m < MIP; m++) part[(half * MIP + m) * 128 + l] = acc[m];
    __syncthreads();

    if (tid < 128) {
#pragma unroll
        for (int m = 0; m < MIP; m++) {
            const float s2  = part[m * 128 + tid] + part[(MIP + m) * 128 + tid];
            const float scale = bn1_g[m] * rsqrtf(bn1_v[m] + EPS);
            const float val = (s2 - bn1_m[m]) * scale + bn1_b[m];
            g_y[(size_t)b * (MIP * 128) + m * 128 + tid] =
                val * fminf(fmaxf(val + 3.f, 0.f), 6.f) * (1.f / 6.f);
        }
    }
}

// ---------------------------------------------------------------------------
// Kernel 3: per (b,c) block: compute a_h[64], a_w[64] from y (8 FMAs each),
// then stream out = x * a_h[h] * a_w[w].  Slice = 4096 floats = 1024 float4.
// ---------------------------------------------------------------------------
__global__ __launch_bounds__(256) void k_apply(
    const float* __restrict__ x,
    const float* __restrict__ convh_w, const float* __restrict__ convw_w,
    float* __restrict__ out)
{
    __shared__ __align__(16) float ysm[MIP * 128];  // 4 KB
    __shared__ __align__(16) float ah[64];
    __shared__ __align__(16) float aw[64];

    const int bc  = blockIdx.x;
    const int b   = bc >> 8;
    const int c   = bc & 255;
    const int tid = threadIdx.x;

    // stage y[b] (1024 floats = 256 float4), L2-hot (reused by 256 blocks/batch)
    ((float4*)ysm)[tid] = ((const float4*)(g_y + (size_t)b * (MIP * 128)))[tid];
    __syncthreads();

    if (tid < 128) {
        const int l   = tid & 63;
        const int off = (tid < 64) ? 0 : 64;
        const float* wp = ((tid < 64) ? convh_w : convw_w) + c * MIP;
        float s = 0.f;
#pragma unroll
        for (int m = 0; m < MIP; m++) s += wp[m] * ysm[m * 128 + off + l];
        const float a = 1.f / (1.f + __expf(-s));
        if (tid < 64) ah[l] = a; else aw[l] = a;
    }
    __syncthreads();

    const float4* x4 = (const float4*)(x + (size_t)bc * (NH * NW));
    float4*       o4 = (float4*)(out + (size_t)bc * (NH * NW));
#pragma unroll
    for (int i = 0; i < 4; i++) {
        const int f  = tid + i * 256;     // 0..1023  (float4 index in slice)
        const int h  = f >> 4;            // 0..63
        const int w4 = f & 15;            // 0..15
        const float4 xv = x4[f];
        const float  a1 = ah[h];
        const float4 a2 = ((const float4*)aw)[w4];
        float4 o;
        o.x = xv.x * a1 * a2.x;
        o.y = xv.y * a1 * a2.y;
        o.z = xv.z * a1 * a2.z;
        o.w = xv.w * a1 * a2.w;
        o4[f] = o;
    }
}

// ---------------------------------------------------------------------------
extern "C" void kernel_launch(void* const* d_in, const int* in_sizes, int n_in,
                              void* d_out, int out_size)
{
    const float* x       = (const float*)d_in[0];
    const float* sph_w3  = (const float*)d_in[1];
    const float* sph_w7  = (const float*)d_in[2];
    const float* sph_g   = (const float*)d_in[3];
    const float* sph_b   = (const float*)d_in[4];
    const float* sph_m   = (const float*)d_in[5];
    const float* sph_v   = (const float*)d_in[6];
    const float* spw_w3  = (const float*)d_in[7];
    const float* spw_w7  = (const float*)d_in[8];
    const float* spw_g   = (const float*)d_in[9];
    const float* spw_b   = (const float*)d_in[10];
    const float* spw_m   = (const float*)d_in[11];
    const float* spw_v   = (const float*)d_in[12];
    const float* conv1_w = (const float*)d_in[13];
    const float* bn1_g   = (const float*)d_in[14];
    const float* bn1_b   = (const float*)d_in[15];
    const float* bn1_m   = (const float*)d_in[16];
    const float* bn1_v   = (const float*)d_in[17];
    const float* convh_w = (const float*)d_in[18];
    const float* convw_w = (const float*)d_in[19];
    float* out = (float*)d_out;

    k_reduce_strip<<<NB * NC, 256>>>(x,
        sph_w3, sph_w7, sph_g, sph_b, sph_m, sph_v,
        spw_w3, spw_w7, spw_g, spw_b, spw_m, spw_v);

    k_y<<<NB, 256>>>(conv1_w, bn1_g, bn1_b, bn1_m, bn1_v);

    k_apply<<<NB * NC, 256>>>(x, convh_w, convw_w, out);
}

// round 4
// speedup vs baseline: 1.8260x; 1.2061x over previous
#include <cuda_runtime.h>
#include <math.h>

#define NB 32
#define NC 256
#define NH 64
#define NW 64
#define MIP 8
#define EPS 1e-5f

// Intermediates (no allocation allowed -> device globals)
__device__ __align__(16) float g_s [NB * NC * 128];   // strip-pooled+BN : 4 MB
__device__ __align__(16) float g_y [NB * MIP * 128];  // conv1+BN+hswish : 128 KB
__device__ __align__(16) float g_ah[NB * NC * NH];    // 2 MB
__device__ __align__(16) float g_aw[NB * NC * NW];    // 2 MB

// ---------------------------------------------------------------------------
// Kernel 1: per (b,c) slice -> row/col means -> depthwise conv3+conv7 -> BN
// ---------------------------------------------------------------------------
__global__ __launch_bounds__(256) void k_reduce_strip(
    const float* __restrict__ x,
    const float* __restrict__ sph_w3, const float* __restrict__ sph_w7,
    const float* __restrict__ sph_g,  const float* __restrict__ sph_b,
    const float* __restrict__ sph_m,  const float* __restrict__ sph_v,
    const float* __restrict__ spw_w3, const float* __restrict__ spw_w7,
    const float* __restrict__ spw_g,  const float* __restrict__ spw_b,
    const float* __restrict__ spw_m,  const float* __restrict__ spw_v)
{
    __shared__ __align__(16) float4 csum[256];   // per-thread column partials
    __shared__ float  mrow[NH];
    __shared__ float  mcol[NW];

    const int bc  = blockIdx.x;       // b*256 + c
    const int c   = bc & (NC - 1);
    const int tid = threadIdx.x;      // 0..255
    const int grp = tid >> 4;         // 0..15 (row-group)
    const int w4  = tid & 15;         // which float4 along W

    const float4* x4 = (const float4*)(x + (size_t)bc * (NH * NW));
    float4 v0 = x4[tid];
    float4 v1 = x4[tid + 256];
    float4 v2 = x4[tid + 512];
    float4 v3 = x4[tid + 768];

    float4 cs;
    cs.x = v0.x + v1.x + v2.x + v3.x;
    cs.y = v0.y + v1.y + v2.y + v3.y;
    cs.z = v0.z + v1.z + v2.z + v3.z;
    cs.w = v0.w + v1.w + v2.w + v3.w;
    csum[tid] = cs;

    float r0 = v0.x + v0.y + v0.z + v0.w;
    float r1 = v1.x + v1.y + v1.z + v1.w;
    float r2 = v2.x + v2.y + v2.z + v2.w;
    float r3 = v3.x + v3.y + v3.z + v3.w;
#pragma unroll
    for (int m = 8; m >= 1; m >>= 1) {
        r0 += __shfl_xor_sync(0xffffffffu, r0, m);
        r1 += __shfl_xor_sync(0xffffffffu, r1, m);
        r2 += __shfl_xor_sync(0xffffffffu, r2, m);
        r3 += __shfl_xor_sync(0xffffffffu, r3, m);
    }
    if (w4 == 0) {
        mrow[grp]      = r0 * (1.f / 64.f);
        mrow[grp + 16] = r1 * (1.f / 64.f);
        mrow[grp + 32] = r2 * (1.f / 64.f);
        mrow[grp + 48] = r3 * (1.f / 64.f);
    }
    __syncthreads();

    if (tid < 64) {
        const float* cf = (const float*)csum;
        float s = 0.f;
#pragma unroll
        for (int g = 0; g < 16; g++) s += cf[g * 64 + tid];
        mcol[tid] = s * (1.f / 64.f);
    }
    __syncthreads();

    if (tid < 128) {
        const int l = tid & 63;
        const float* src; const float* w3; const float* w7;
        float g, bb, mm, vv; int off;
        if (tid < 64) {
            src = mrow; w3 = sph_w3 + c * 3; w7 = sph_w7 + c * 7;
            g = sph_g[c]; bb = sph_b[c]; mm = sph_m[c]; vv = sph_v[c]; off = 0;
        } else {
            src = mcol; w3 = spw_w3 + c * 3; w7 = spw_w7 + c * 7;
            g = spw_g[c]; bb = spw_b[c]; mm = spw_m[c]; vv = spw_v[c]; off = 64;
        }

        float acc = src[l];
#pragma unroll
        for (int j = 0; j < 3; j++) {
            int idx = l + j - 1;
            if (idx >= 0 && idx < 64) acc += src[idx] * w3[j];
        }
#pragma unroll
        for (int j = 0; j < 7; j++) {
            int idx = l + j - 3;
            if (idx >= 0 && idx < 64) acc += src[idx] * w7[j];
        }
        acc *= (1.f / 3.f);
        const float scale = g * rsqrtf(vv + EPS);
        g_s[(size_t)bc * 128 + off + l] = (acc - mm) * scale + bb;
    }
}

// ---------------------------------------------------------------------------
// Kernel 2: per batch: conv1 (C->MIP) + BN1 + hswish -> g_y.
// ---------------------------------------------------------------------------
__global__ __launch_bounds__(256) void k_y(
    const float* __restrict__ conv1_w,
    const float* __restrict__ bn1_g, const float* __restrict__ bn1_b,
    const float* __restrict__ bn1_m, const float* __restrict__ bn1_v)
{
    __shared__ float w1s[MIP * NC];       // 8 KB
    __shared__ float part[2 * MIP * 128]; // 8 KB

    const int b    = blockIdx.x;
    const int tid  = threadIdx.x;
    const int half = tid >> 7;
    const int l    = tid & 127;

#pragma unroll
    for (int i = 0; i < MIP; i++) w1s[tid + i * NC] = conv1_w[tid + i * NC];
    __syncthreads();

    float acc[MIP];
#pragma unroll
    for (int m = 0; m < MIP; m++) acc[m] = 0.f;

    const float* sp = g_s + (size_t)b * NC * 128 + half * 128 * 128 + l;
#pragma unroll 4
    for (int cc = 0; cc < 128; cc++) {
        const float v = sp[(size_t)cc * 128];
#pragma unroll
        for (int m = 0; m < MIP; m++) acc[m] += w1s[m * NC + half * 128 + cc] * v;
    }
#pragma unroll
    for (int m = 0; m < MIP; m++) part[(half * MIP + m) * 128 + l] = acc[m];
    __syncthreads();

    if (tid < 128) {
#pragma unroll
        for (int m = 0; m < MIP; m++) {
            const float s2    = part[m * 128 + tid] + part[(MIP + m) * 128 + tid];
            const float scale = bn1_g[m] * rsqrtf(bn1_v[m] + EPS);
            const float val   = (s2 - bn1_m[m]) * scale + bn1_b[m];
            g_y[(size_t)b * (MIP * 128) + m * 128 + tid] =
                val * fminf(fmaxf(val + 3.f, 0.f), 6.f) * (1.f / 6.f);
        }
    }
}

// ---------------------------------------------------------------------------
// Kernel 2b: attention weights. One block per (b,c), 128 threads.
// thread <64: ah[l]; thread >=64: aw[l]. y[b] is L2-hot (4 KB reused x256).
// ---------------------------------------------------------------------------
__global__ __launch_bounds__(128) void k_att(
    const float* __restrict__ convh_w, const float* __restrict__ convw_w)
{
    const int bc  = blockIdx.x;
    const int b   = bc >> 8;
    const int c   = bc & 255;
    const int tid = threadIdx.x;
    const int l   = tid & 63;
    const int off = (tid < 64) ? 0 : 64;

    const float* yb = g_y + (size_t)b * (MIP * 128) + off + l;
    const float* wp = ((tid < 64) ? convh_w : convw_w) + c * MIP;

    float s = 0.f;
#pragma unroll
    for (int m = 0; m < MIP; m++) s += wp[m] * yb[m * 128];
    const float a = 1.f / (1.f + __expf(-s));
    ((tid < 64) ? g_ah : g_aw)[bc * 64 + l] = a;
}

// ---------------------------------------------------------------------------
// Kernel 3: pure stream: out = x * ah[h] * aw[w]. No smem, no syncs.
// Blocks process bc in REVERSE so the first reads hit the x tail still in L2.
// ---------------------------------------------------------------------------
__global__ __launch_bounds__(256) void k_apply(
    const float* __restrict__ x, float* __restrict__ out)
{
    const int bc  = (NB * NC - 1) - blockIdx.x;
    const int tid = threadIdx.x;

    const float4* x4  = (const float4*)(x   + (size_t)bc * (NH * NW));
    float4*       o4  = (float4*)      (out + (size_t)bc * (NH * NW));
    const float*  ahp = g_ah + bc * 64;
    const float4* awp = (const float4*)(g_aw + bc * 64);

#pragma unroll
    for (int i = 0; i < 4; i++) {
        const int f  = tid + i * 256;    // 0..1023
        const int h  = f >> 4;           // 0..63
        const int w4 = f & 15;           // 0..15
        const float4 xv = __ldg(&x4[f]);
        const float  a1 = __ldg(&ahp[h]);
        const float4 a2 = __ldg(&awp[w4]);
        float4 o;
        o.x = xv.x * a1 * a2.x;
        o.y = xv.y * a1 * a2.y;
        o.z = xv.z * a1 * a2.z;
        o.w = xv.w * a1 * a2.w;
        o4[f] = o;
    }
}

// ---------------------------------------------------------------------------
extern "C" void kernel_launch(void* const* d_in, const int* in_sizes, int n_in,
                              void* d_out, int out_size)
{
    const float* x       = (const float*)d_in[0];
    const float* sph_w3  = (const float*)d_in[1];
    const float* sph_w7  = (const float*)d_in[2];
    const float* sph_g   = (const float*)d_in[3];
    const float* sph_b   = (const float*)d_in[4];
    const float* sph_m   = (const float*)d_in[5];
    const float* sph_v   = (const float*)d_in[6];
    const float* spw_w3  = (const float*)d_in[7];
    const float* spw_w7  = (const float*)d_in[8];
    const float* spw_g   = (const float*)d_in[9];
    const float* spw_b   = (const float*)d_in[10];
    const float* spw_m   = (const float*)d_in[11];
    const float* spw_v   = (const float*)d_in[12];
    const float* conv1_w = (const float*)d_in[13];
    const float* bn1_g   = (const float*)d_in[14];
    const float* bn1_b   = (const float*)d_in[15];
    const float* bn1_m   = (const float*)d_in[16];
    const float* bn1_v   = (const float*)d_in[17];
    const float* convh_w = (const float*)d_in[18];
    const float* convw_w = (const float*)d_in[19];
    float* out = (float*)d_out;

    k_reduce_strip<<<NB * NC, 256>>>(x,
        sph_w3, sph_w7, sph_g, sph_b, sph_m, sph_v,
        spw_w3, spw_w7, spw_g, spw_b, spw_m, spw_v);

    k_y<<<NB, 256>>>(conv1_w, bn1_g, bn1_b, bn1_m, bn1_v);

    k_att<<<NB * NC, 128>>>(convh_w, convw_w);

    k_apply<<<NB * NC, 256>>>(x, out);
}